// round 12
// baseline (speedup 1.0000x reference)
#include <cuda_runtime.h>
#include <cuda_bf16.h>

#define BB 4
#define TP 2048
#define TE 16384
#define DD 64
#define NBKT 1024
#define CAP 128
#define FINF 3.402823466e38f

// Scratch (allocation-free rule -> __device__ globals; zero-init at load).
// g_bar_cnt invariant: zero at kernel_launch entry (gather resets after a
// block-wide barrier that orders all reads before the reset).
__device__ int g_bar_cnt[BB * TP];
__device__ int g_ev_list[BB * TP][CAP];

__device__ __forceinline__ int warp_incl_scan(int v, int lane) {
    #pragma unroll
    for (int off = 1; off < 32; off <<= 1) {
        int u = __shfl_up_sync(0xffffffffu, v, off);
        if (lane >= off) v += u;
    }
    return v;
}

// ---------------------------------------------------------------------------
// K1: each block independently builds the price-bucket structure in its own
// smem (no cross-block sync), then runs the exact argmin for its 256 events
// and claims slots. Grid (64, BB) x 256.   [unchanged — R10-proven]
// ---------------------------------------------------------------------------
__global__ __launch_bounds__(256) void k_align(
    const float* __restrict__ price_ts,
    const float* __restrict__ event_ts)
{
    __shared__ float sk[TP];
    __shared__ int   si[TP];
    __shared__ int   sbs[NBKT + 1];
    __shared__ int   cnt[NBKT];
    __shared__ int   wsum[8];

    const int t = threadIdx.x;
    const int lane = t & 31, wid = t >> 5;
    const int x = blockIdx.x;          // 0..63
    const int b = blockIdx.y;          // 0..BB-1

    const int e = x * 256 + t;
    const float et = event_ts[b * TE + e];

    #pragma unroll
    for (int i = t; i < NBKT; i += 256) cnt[i] = 0;

    float pv[8]; int kb[8];
    #pragma unroll
    for (int j = 0; j < 8; ++j) {
        pv[j] = price_ts[b * TP + t + 256 * j];
        kb[j] = min((int)(pv[j] * (float)NBKT), NBKT - 1);
    }
    __syncthreads();
    #pragma unroll
    for (int j = 0; j < 8; ++j) atomicAdd(&cnt[kb[j]], 1);
    __syncthreads();

    const int c0 = cnt[4 * t], c1 = cnt[4 * t + 1];
    const int c2 = cnt[4 * t + 2], c3 = cnt[4 * t + 3];
    const int ts = c0 + c1 + c2 + c3;
    int incl = warp_incl_scan(ts, lane);
    if (lane == 31) wsum[wid] = incl;
    __syncthreads();
    if (t == 0) {
        int acc = 0;
        #pragma unroll
        for (int w = 0; w < 8; ++w) { int v = wsum[w]; wsum[w] = acc; acc += v; }
    }
    __syncthreads();
    const int base = wsum[wid] + (incl - ts);
    sbs[4 * t]     = base;
    sbs[4 * t + 1] = base + c0;
    sbs[4 * t + 2] = base + c0 + c1;
    sbs[4 * t + 3] = base + c0 + c1 + c2;
    if (t == 0) sbs[NBKT] = TP;
    #pragma unroll
    for (int i = t; i < NBKT; i += 256) cnt[i] = 0;
    __syncthreads();

    #pragma unroll
    for (int j = 0; j < 8; ++j) {
        const int pos = sbs[kb[j]] + atomicAdd(&cnt[kb[j]], 1);
        sk[pos] = pv[j];
        si[pos] = t + 256 * j;
    }
    __syncthreads();

    const int bkt = min(max((int)(et * (float)NBKT), 0), NBKT - 1);
    float best = FINF;
    int   bi   = 0x7fffffff;

    {
        const int j0 = sbs[max(bkt - 1, 0)];
        const int j1 = sbs[min(bkt + 1, NBKT - 1) + 1];
        for (int j = j0; j < j1; ++j) {
            const float d = fabsf(et - sk[j]);
            const int   ix = si[j];
            if (d < best || (d == best && ix < bi)) { best = d; bi = ix; }
        }
    }
    int r = 1;
    while (true) {
        const int lb = bkt - r - 1, rb = bkt + r + 1;
        const bool lv = (lb >= 0), rv = (rb <= NBKT - 1);
        const float lB = lv ? (et - (float)(bkt - r) / (float)NBKT) : FINF;
        const float rB = rv ? ((float)rb / (float)NBKT - et) : FINF;
        const bool needL = lv && !(best < lB);
        const bool needR = rv && !(best < rB);
        if (!needL && !needR) break;
        if (needL)
            for (int j = sbs[lb]; j < sbs[lb + 1]; ++j) {
                const float d = fabsf(et - sk[j]);
                const int ix = si[j];
                if (d < best || (d == best && ix < bi)) { best = d; bi = ix; }
            }
        if (needR)
            for (int j = sbs[rb]; j < sbs[rb + 1]; ++j) {
                const float d = fabsf(et - sk[j]);
                const int ix = si[j];
                if (d < best || (d == best && ix < bi)) { best = d; bi = ix; }
            }
        ++r;
    }

    const int slot = atomicAdd(&g_bar_cnt[b * TP + bi], 1);
    if (slot < CAP) g_ev_list[b * TP + bi][slot] = e;
}

// ---------------------------------------------------------------------------
// K2: gather + mean + coverage. Each 64-thread group pipelines TWO rows:
// both counts, then both ID sets, then 16 independent value loads per
// iteration. Grid = 1024 blocks = one wave. Race-free counter reset.
// ---------------------------------------------------------------------------
__global__ __launch_bounds__(256) void k_gather(
    const float* __restrict__ event_vals,
    float* __restrict__ out, int has_cov)
{
    const int grp = threadIdx.x >> 6;           // 0..3
    const int d   = threadIdx.x & 63;
    const int rowA = blockIdx.x * 8 + grp * 2;  // 8 rows per block
    const int rowB = rowA + 1;                  // same batch (2048 % 8 == 0)
    const int b = rowA >> 11;

    // both counts issued back-to-back (independent loads)
    const int nA = g_bar_cnt[rowA];
    const int nB = g_bar_cnt[rowB];
    __syncthreads();                            // all reads before the reset
    if (d == 0) { g_bar_cnt[rowA] = 0; g_bar_cnt[rowB] = 0; }

    const int mA = min(nA, CAP);
    const int mB = min(nB, CAP);
    const int* lstA = g_ev_list[rowA];
    const int* lstB = g_ev_list[rowB];

    const float* base = event_vals + (size_t)b * TE * DD + d;

    float s[8];
    #pragma unroll
    for (int k = 0; k < 8; ++k) s[k] = 0.0f;
    float u[8];
    #pragma unroll
    for (int k = 0; k < 8; ++k) u[k] = 0.0f;

    const int mm = max(mA, mB);
    for (int j0 = 0; j0 < mm; j0 += 8) {
        // phase 1: 16 broadcast ID loads (both rows, independent)
        int idsA[8], idsB[8];
        #pragma unroll
        for (int k = 0; k < 8; ++k) {
            idsA[k] = (j0 + k < mA) ? __ldg(&lstA[j0 + k]) : -1;
            idsB[k] = (j0 + k < mB) ? __ldg(&lstB[j0 + k]) : -1;
        }
        // phase 2: 16 independent value loads into separate accumulators
        #pragma unroll
        for (int k = 0; k < 8; ++k) {
            const float vA = (idsA[k] >= 0)
                           ? __ldg(base + (size_t)idsA[k] * DD) : 0.0f;
            const float vB = (idsB[k] >= 0)
                           ? __ldg(base + (size_t)idsB[k] * DD) : 0.0f;
            s[k] += vA;
            u[k] += vB;
        }
    }

    const float sumA = ((s[0] + s[1]) + (s[2] + s[3]))
                     + ((s[4] + s[5]) + (s[6] + s[7]));
    const float sumB = ((u[0] + u[1]) + (u[2] + u[3]))
                     + ((u[4] + u[5]) + (u[6] + u[7]));

    out[(size_t)rowA * DD + d] = (nA > 0) ? (sumA / (float)nA) : 0.0f;
    out[(size_t)rowB * DD + d] = (nB > 0) ? (sumB / (float)nB) : 0.0f;

    if (has_cov && d == 0) {
        out[(size_t)BB * TP * DD + rowA] = (nA > 0) ? 1.0f : 0.0f;
        out[(size_t)BB * TP * DD + rowB] = (nB > 0) ? 1.0f : 0.0f;
    }
}

// ---------------------------------------------------------------------------
extern "C" void kernel_launch(void* const* d_in, const int* in_sizes, int n_in,
                              void* d_out, int out_size) {
    const float* price_ts   = (const float*)d_in[0];
    const float* event_ts   = (const float*)d_in[1];
    const float* event_vals = (const float*)d_in[2];
    float* out = (float*)d_out;

    const int has_cov = (out_size >= BB * TP * DD + BB * TP) ? 1 : 0;

    dim3 agrid(64, BB);
    k_align<<<agrid, 256>>>(price_ts, event_ts);

    k_gather<<<BB * TP / 8, 256>>>(event_vals, out, has_cov);
}

// round 13
// speedup vs baseline: 1.0108x; 1.0108x over previous
#include <cuda_runtime.h>
#include <cuda_bf16.h>

#define BB 4
#define TP 2048
#define TE 16384
#define DD 64
#define NBKT 1024
#define CAP 128
#define FINF 3.402823466e38f

// Scratch (allocation-free rule -> __device__ globals; zero-init at load).
// g_bar_cnt invariant: zero at kernel_launch entry (gather resets after a
// block-wide barrier that orders all reads before the reset).
__device__ int g_bar_cnt[BB * TP];
__device__ int g_ev_list[BB * TP][CAP];

__device__ __forceinline__ int warp_incl_scan(int v, int lane) {
    #pragma unroll
    for (int off = 1; off < 32; off <<= 1) {
        int u = __shfl_up_sync(0xffffffffu, v, off);
        if (lane >= off) v += u;
    }
    return v;
}

// ---------------------------------------------------------------------------
// K1: each block independently builds the price-bucket structure in its own
// smem (no cross-block sync), then runs the exact argmin for its 256 events
// and claims slots. Grid (64, BB) x 256.   [unchanged — R10-proven]
// ---------------------------------------------------------------------------
__global__ __launch_bounds__(256) void k_align(
    const float* __restrict__ price_ts,
    const float* __restrict__ event_ts)
{
    __shared__ float sk[TP];
    __shared__ int   si[TP];
    __shared__ int   sbs[NBKT + 1];
    __shared__ int   cnt[NBKT];
    __shared__ int   wsum[8];

    const int t = threadIdx.x;
    const int lane = t & 31, wid = t >> 5;
    const int x = blockIdx.x;          // 0..63
    const int b = blockIdx.y;          // 0..BB-1

    const int e = x * 256 + t;
    const float et = event_ts[b * TE + e];

    #pragma unroll
    for (int i = t; i < NBKT; i += 256) cnt[i] = 0;

    float pv[8]; int kb[8];
    #pragma unroll
    for (int j = 0; j < 8; ++j) {
        pv[j] = price_ts[b * TP + t + 256 * j];
        kb[j] = min((int)(pv[j] * (float)NBKT), NBKT - 1);
    }
    __syncthreads();
    #pragma unroll
    for (int j = 0; j < 8; ++j) atomicAdd(&cnt[kb[j]], 1);
    __syncthreads();

    const int c0 = cnt[4 * t], c1 = cnt[4 * t + 1];
    const int c2 = cnt[4 * t + 2], c3 = cnt[4 * t + 3];
    const int ts = c0 + c1 + c2 + c3;
    int incl = warp_incl_scan(ts, lane);
    if (lane == 31) wsum[wid] = incl;
    __syncthreads();
    if (t == 0) {
        int acc = 0;
        #pragma unroll
        for (int w = 0; w < 8; ++w) { int v = wsum[w]; wsum[w] = acc; acc += v; }
    }
    __syncthreads();
    const int base = wsum[wid] + (incl - ts);
    sbs[4 * t]     = base;
    sbs[4 * t + 1] = base + c0;
    sbs[4 * t + 2] = base + c0 + c1;
    sbs[4 * t + 3] = base + c0 + c1 + c2;
    if (t == 0) sbs[NBKT] = TP;
    #pragma unroll
    for (int i = t; i < NBKT; i += 256) cnt[i] = 0;
    __syncthreads();

    #pragma unroll
    for (int j = 0; j < 8; ++j) {
        const int pos = sbs[kb[j]] + atomicAdd(&cnt[kb[j]], 1);
        sk[pos] = pv[j];
        si[pos] = t + 256 * j;
    }
    __syncthreads();

    const int bkt = min(max((int)(et * (float)NBKT), 0), NBKT - 1);
    float best = FINF;
    int   bi   = 0x7fffffff;

    {
        const int j0 = sbs[max(bkt - 1, 0)];
        const int j1 = sbs[min(bkt + 1, NBKT - 1) + 1];
        for (int j = j0; j < j1; ++j) {
            const float d = fabsf(et - sk[j]);
            const int   ix = si[j];
            if (d < best || (d == best && ix < bi)) { best = d; bi = ix; }
        }
    }
    int r = 1;
    while (true) {
        const int lb = bkt - r - 1, rb = bkt + r + 1;
        const bool lv = (lb >= 0), rv = (rb <= NBKT - 1);
        const float lB = lv ? (et - (float)(bkt - r) / (float)NBKT) : FINF;
        const float rB = rv ? ((float)rb / (float)NBKT - et) : FINF;
        const bool needL = lv && !(best < lB);
        const bool needR = rv && !(best < rB);
        if (!needL && !needR) break;
        if (needL)
            for (int j = sbs[lb]; j < sbs[lb + 1]; ++j) {
                const float d = fabsf(et - sk[j]);
                const int ix = si[j];
                if (d < best || (d == best && ix < bi)) { best = d; bi = ix; }
            }
        if (needR)
            for (int j = sbs[rb]; j < sbs[rb + 1]; ++j) {
                const float d = fabsf(et - sk[j]);
                const int ix = si[j];
                if (d < best || (d == best && ix < bi)) { best = d; bi = ix; }
            }
        ++r;
    }

    const int slot = atomicAdd(&g_bar_cnt[b * TP + bi], 1);
    if (slot < CAP) g_ev_list[b * TP + bi][slot] = e;
}

// ---------------------------------------------------------------------------
// K2: gather + mean + coverage. 128 threads per row (two 64-wide halves,
// each summing a strided half of the row's events), 2 rows per block,
// grid 4096. Shorter per-thread chains, 2x independent chains vs R10.
// Race-free counter reset (read -> barrier -> reset).
// ---------------------------------------------------------------------------
__global__ __launch_bounds__(256) void k_gather(
    const float* __restrict__ event_vals,
    float* __restrict__ out, int has_cov)
{
    __shared__ float part[256];

    const int t    = threadIdx.x;
    const int sub  = t >> 7;                    // row within block: 0..1
    const int tid  = t & 127;                   // thread within row
    const int half = tid >> 6;                  // 0..1
    const int d    = tid & 63;
    const int row  = blockIdx.x * 2 + sub;      // 0 .. B*TP-1
    const int b    = row >> 11;

    const int n = g_bar_cnt[row];               // every thread reads first
    __syncthreads();                            // all reads ordered before...
    if (tid == 0) g_bar_cnt[row] = 0;           // ...the reset (race-free)

    const int m = min(n, CAP);
    const int* lst = g_ev_list[row];
    const float* base = event_vals + (size_t)b * TE * DD + d;

    // this half handles events half, half+2, half+4, ... (4-way MLP)
    float s0 = 0.f, s1 = 0.f, s2 = 0.f, s3 = 0.f;
    for (int j0 = half; j0 < m; j0 += 8) {
        const int i1 = j0 + 2, i2 = j0 + 4, i3 = j0 + 6;
        const int e0 = __ldg(&lst[j0]);
        const int e1 = (i1 < m) ? __ldg(&lst[i1]) : -1;
        const int e2 = (i2 < m) ? __ldg(&lst[i2]) : -1;
        const int e3 = (i3 < m) ? __ldg(&lst[i3]) : -1;
        s0 += __ldg(base + (size_t)e0 * DD);
        s1 += (e1 >= 0) ? __ldg(base + (size_t)e1 * DD) : 0.0f;
        s2 += (e2 >= 0) ? __ldg(base + (size_t)e2 * DD) : 0.0f;
        s3 += (e3 >= 0) ? __ldg(base + (size_t)e3 * DD) : 0.0f;
    }
    part[t] = (s0 + s1) + (s2 + s3);
    __syncthreads();

    if (half == 0) {
        const float sum = part[t] + part[t + 64];
        out[(size_t)row * DD + d] = (n > 0) ? (sum / (float)n) : 0.0f;
        if (has_cov && d == 0)
            out[(size_t)BB * TP * DD + row] = (n > 0) ? 1.0f : 0.0f;
    }
}

// ---------------------------------------------------------------------------
extern "C" void kernel_launch(void* const* d_in, const int* in_sizes, int n_in,
                              void* d_out, int out_size) {
    const float* price_ts   = (const float*)d_in[0];
    const float* event_ts   = (const float*)d_in[1];
    const float* event_vals = (const float*)d_in[2];
    float* out = (float*)d_out;

    const int has_cov = (out_size >= BB * TP * DD + BB * TP) ? 1 : 0;

    dim3 agrid(64, BB);
    k_align<<<agrid, 256>>>(price_ts, event_ts);

    k_gather<<<BB * TP / 2, 256>>>(event_vals, out, has_cov);
}

// round 14
// speedup vs baseline: 1.3776x; 1.3629x over previous
#include <cuda_runtime.h>
#include <cuda_bf16.h>

#define BB 4
#define TP 2048
#define TE 16384
#define DD 64
#define NBKT 1024
#define CAP 128
#define FINF 3.402823466e38f

// Scratch (allocation-free rule -> __device__ globals; zero-init at load).
// g_bar_cnt invariant: zero at kernel_launch entry (gather resets after a
// block-wide barrier that orders all reads before the reset).
__device__ int g_bar_cnt[BB * TP];
__device__ int g_ev_list[BB * TP][CAP];

__device__ __forceinline__ int warp_incl_scan(int v, int lane) {
    #pragma unroll
    for (int off = 1; off < 32; off <<= 1) {
        int u = __shfl_up_sync(0xffffffffu, v, off);
        if (lane >= off) v += u;
    }
    return v;
}

// ---------------------------------------------------------------------------
// K1: each block independently builds the price-bucket structure in its own
// smem (no cross-block sync), then runs the exact argmin for its 256 events
// and claims slots. Grid (64, BB) x 256.   [unchanged — R10-proven]
// ---------------------------------------------------------------------------
__global__ __launch_bounds__(256) void k_align(
    const float* __restrict__ price_ts,
    const float* __restrict__ event_ts)
{
    __shared__ float sk[TP];
    __shared__ int   si[TP];
    __shared__ int   sbs[NBKT + 1];
    __shared__ int   cnt[NBKT];
    __shared__ int   wsum[8];

    const int t = threadIdx.x;
    const int lane = t & 31, wid = t >> 5;
    const int x = blockIdx.x;          // 0..63
    const int b = blockIdx.y;          // 0..BB-1

    const int e = x * 256 + t;
    const float et = event_ts[b * TE + e];

    #pragma unroll
    for (int i = t; i < NBKT; i += 256) cnt[i] = 0;

    float pv[8]; int kb[8];
    #pragma unroll
    for (int j = 0; j < 8; ++j) {
        pv[j] = price_ts[b * TP + t + 256 * j];
        kb[j] = min((int)(pv[j] * (float)NBKT), NBKT - 1);
    }
    __syncthreads();
    #pragma unroll
    for (int j = 0; j < 8; ++j) atomicAdd(&cnt[kb[j]], 1);
    __syncthreads();

    const int c0 = cnt[4 * t], c1 = cnt[4 * t + 1];
    const int c2 = cnt[4 * t + 2], c3 = cnt[4 * t + 3];
    const int ts = c0 + c1 + c2 + c3;
    int incl = warp_incl_scan(ts, lane);
    if (lane == 31) wsum[wid] = incl;
    __syncthreads();
    if (t == 0) {
        int acc = 0;
        #pragma unroll
        for (int w = 0; w < 8; ++w) { int v = wsum[w]; wsum[w] = acc; acc += v; }
    }
    __syncthreads();
    const int base = wsum[wid] + (incl - ts);
    sbs[4 * t]     = base;
    sbs[4 * t + 1] = base + c0;
    sbs[4 * t + 2] = base + c0 + c1;
    sbs[4 * t + 3] = base + c0 + c1 + c2;
    if (t == 0) sbs[NBKT] = TP;
    #pragma unroll
    for (int i = t; i < NBKT; i += 256) cnt[i] = 0;
    __syncthreads();

    #pragma unroll
    for (int j = 0; j < 8; ++j) {
        const int pos = sbs[kb[j]] + atomicAdd(&cnt[kb[j]], 1);
        sk[pos] = pv[j];
        si[pos] = t + 256 * j;
    }
    __syncthreads();

    const int bkt = min(max((int)(et * (float)NBKT), 0), NBKT - 1);
    float best = FINF;
    int   bi   = 0x7fffffff;

    {
        const int j0 = sbs[max(bkt - 1, 0)];
        const int j1 = sbs[min(bkt + 1, NBKT - 1) + 1];
        for (int j = j0; j < j1; ++j) {
            const float d = fabsf(et - sk[j]);
            const int   ix = si[j];
            if (d < best || (d == best && ix < bi)) { best = d; bi = ix; }
        }
    }
    int r = 1;
    while (true) {
        const int lb = bkt - r - 1, rb = bkt + r + 1;
        const bool lv = (lb >= 0), rv = (rb <= NBKT - 1);
        const float lB = lv ? (et - (float)(bkt - r) / (float)NBKT) : FINF;
        const float rB = rv ? ((float)rb / (float)NBKT - et) : FINF;
        const bool needL = lv && !(best < lB);
        const bool needR = rv && !(best < rB);
        if (!needL && !needR) break;
        if (needL)
            for (int j = sbs[lb]; j < sbs[lb + 1]; ++j) {
                const float d = fabsf(et - sk[j]);
                const int ix = si[j];
                if (d < best || (d == best && ix < bi)) { best = d; bi = ix; }
            }
        if (needR)
            for (int j = sbs[rb]; j < sbs[rb + 1]; ++j) {
                const float d = fabsf(et - sk[j]);
                const int ix = si[j];
                if (d < best || (d == best && ix < bi)) { best = d; bi = ix; }
            }
        ++r;
    }

    const int slot = atomicAdd(&g_bar_cnt[b * TP + bi], 1);
    if (slot < CAP) g_ev_list[b * TP + bi][slot] = e;
}

// ---------------------------------------------------------------------------
// K2: gather with FLOAT4 value loads. 64-thread group per bar arranged as
// (q in [0,4)) x (d4 in [0,16)): thread loads float4 of dims [4*d4,4*d4+4)
// for events j == q (mod 4), 2-deep unroll (8 events/iter = mean bar count).
// Reduce over q: shfl_xor(16) intra-warp + one smem float4 exchange.
// Grid 2048 (4 bars/block). Race-free counter reset (R10 protocol).
// ---------------------------------------------------------------------------
__global__ __launch_bounds__(256) void k_gather(
    const float* __restrict__ event_vals,
    float* __restrict__ out, int has_cov)
{
    __shared__ float4 xch[4][16];

    const int t   = threadIdx.x;
    const int grp = t >> 6;                     // 0..3 (bar within block)
    const int tg  = t & 63;                     // thread within group
    const int q   = tg >> 4;                    // 0..3 (event lane)
    const int d4  = tg & 15;                    // 0..15 (float4 chunk of dims)
    const int row = blockIdx.x * 4 + grp;       // 0 .. B*TP-1
    const int b   = row >> 11;

    const int n = g_bar_cnt[row];               // every thread reads first
    __syncthreads();                            // all reads ordered before...
    if (tg == 0) g_bar_cnt[row] = 0;            // ...the reset (race-free)

    const int m = min(n, CAP);
    const int* lst = g_ev_list[row];

    // base points at float4 chunk d4 of event 0 of this batch
    const float4* base =
        reinterpret_cast<const float4*>(event_vals + (size_t)b * TE * DD) + d4;

    float4 acc = make_float4(0.f, 0.f, 0.f, 0.f);

    for (int j0 = 0; j0 < m; j0 += 8) {
        const int ja = j0 + q;
        const int jb = j0 + 4 + q;
        const int ea = (ja < m) ? __ldg(&lst[ja]) : -1;
        const int eb = (jb < m) ? __ldg(&lst[jb]) : -1;
        if (ea >= 0) {                           // LDG.128, 2 independent
            const float4 v = __ldg(base + (size_t)ea * (DD / 4));
            acc.x += v.x; acc.y += v.y; acc.z += v.z; acc.w += v.w;
        }
        if (eb >= 0) {
            const float4 v = __ldg(base + (size_t)eb * (DD / 4));
            acc.x += v.x; acc.y += v.y; acc.z += v.z; acc.w += v.w;
        }
    }

    // reduce over q. intra-warp: q pairs (0,1) and (2,3) via xor-16
    acc.x += __shfl_xor_sync(0xffffffffu, acc.x, 16);
    acc.y += __shfl_xor_sync(0xffffffffu, acc.y, 16);
    acc.z += __shfl_xor_sync(0xffffffffu, acc.z, 16);
    acc.w += __shfl_xor_sync(0xffffffffu, acc.w, 16);

    // cross-warp: q==2 lanes publish, q==0 lanes combine + write
    if (q == 2) xch[grp][d4] = acc;
    __syncthreads();

    if (q == 0) {
        const float4 o = xch[grp][d4];
        const float inv = (n > 0) ? (1.0f / (float)n) : 0.0f;
        float4 r;
        r.x = (acc.x + o.x) * inv;
        r.y = (acc.y + o.y) * inv;
        r.z = (acc.z + o.z) * inv;
        r.w = (acc.w + o.w) * inv;
        reinterpret_cast<float4*>(out)[(size_t)row * (DD / 4) + d4] = r;
        if (has_cov && d4 == 0)
            out[(size_t)BB * TP * DD + row] = (n > 0) ? 1.0f : 0.0f;
    }
}

// ---------------------------------------------------------------------------
extern "C" void kernel_launch(void* const* d_in, const int* in_sizes, int n_in,
                              void* d_out, int out_size) {
    const float* price_ts   = (const float*)d_in[0];
    const float* event_ts   = (const float*)d_in[1];
    const float* event_vals = (const float*)d_in[2];
    float* out = (float*)d_out;

    const int has_cov = (out_size >= BB * TP * DD + BB * TP) ? 1 : 0;

    dim3 agrid(64, BB);
    k_align<<<agrid, 256>>>(price_ts, event_ts);

    k_gather<<<BB * TP / 4, 256>>>(event_vals, out, has_cov);
}

// round 15
// speedup vs baseline: 1.3864x; 1.0064x over previous
#include <cuda_runtime.h>
#include <cuda_bf16.h>

#define BB 4
#define TP 2048
#define TE 16384
#define DD 64
#define NBKT 1024
#define CAP 128
#define FINF 3.402823466e38f

// Scratch (allocation-free rule -> __device__ globals; zero-init at load).
// g_bar_cnt invariant: zero at kernel_launch entry (gather resets after a
// block-wide barrier that orders all reads before the reset).
// g_ev_list invariant: every slot always holds a value in [0, TE) (zero-init,
// only ever overwritten with valid event ids) -> speculative loads are safe.
__device__ int g_bar_cnt[BB * TP];
__device__ int g_ev_list[BB * TP][CAP];

__device__ __forceinline__ int warp_incl_scan(int v, int lane) {
    #pragma unroll
    for (int off = 1; off < 32; off <<= 1) {
        int u = __shfl_up_sync(0xffffffffu, v, off);
        if (lane >= off) v += u;
    }
    return v;
}

// ---------------------------------------------------------------------------
// K1: each block independently builds the price-bucket structure in its own
// smem (no cross-block sync), then runs the exact argmin for its 256 events
// and claims slots. Grid (64, BB) x 256.   [unchanged — R10-proven]
// ---------------------------------------------------------------------------
__global__ __launch_bounds__(256) void k_align(
    const float* __restrict__ price_ts,
    const float* __restrict__ event_ts)
{
    __shared__ float sk[TP];
    __shared__ int   si[TP];
    __shared__ int   sbs[NBKT + 1];
    __shared__ int   cnt[NBKT];
    __shared__ int   wsum[8];

    const int t = threadIdx.x;
    const int lane = t & 31, wid = t >> 5;
    const int x = blockIdx.x;          // 0..63
    const int b = blockIdx.y;          // 0..BB-1

    const int e = x * 256 + t;
    const float et = event_ts[b * TE + e];

    #pragma unroll
    for (int i = t; i < NBKT; i += 256) cnt[i] = 0;

    float pv[8]; int kb[8];
    #pragma unroll
    for (int j = 0; j < 8; ++j) {
        pv[j] = price_ts[b * TP + t + 256 * j];
        kb[j] = min((int)(pv[j] * (float)NBKT), NBKT - 1);
    }
    __syncthreads();
    #pragma unroll
    for (int j = 0; j < 8; ++j) atomicAdd(&cnt[kb[j]], 1);
    __syncthreads();

    const int c0 = cnt[4 * t], c1 = cnt[4 * t + 1];
    const int c2 = cnt[4 * t + 2], c3 = cnt[4 * t + 3];
    const int ts = c0 + c1 + c2 + c3;
    int incl = warp_incl_scan(ts, lane);
    if (lane == 31) wsum[wid] = incl;
    __syncthreads();
    if (t == 0) {
        int acc = 0;
        #pragma unroll
        for (int w = 0; w < 8; ++w) { int v = wsum[w]; wsum[w] = acc; acc += v; }
    }
    __syncthreads();
    const int base = wsum[wid] + (incl - ts);
    sbs[4 * t]     = base;
    sbs[4 * t + 1] = base + c0;
    sbs[4 * t + 2] = base + c0 + c1;
    sbs[4 * t + 3] = base + c0 + c1 + c2;
    if (t == 0) sbs[NBKT] = TP;
    #pragma unroll
    for (int i = t; i < NBKT; i += 256) cnt[i] = 0;
    __syncthreads();

    #pragma unroll
    for (int j = 0; j < 8; ++j) {
        const int pos = sbs[kb[j]] + atomicAdd(&cnt[kb[j]], 1);
        sk[pos] = pv[j];
        si[pos] = t + 256 * j;
    }
    __syncthreads();

    const int bkt = min(max((int)(et * (float)NBKT), 0), NBKT - 1);
    float best = FINF;
    int   bi   = 0x7fffffff;

    {
        const int j0 = sbs[max(bkt - 1, 0)];
        const int j1 = sbs[min(bkt + 1, NBKT - 1) + 1];
        for (int j = j0; j < j1; ++j) {
            const float d = fabsf(et - sk[j]);
            const int   ix = si[j];
            if (d < best || (d == best && ix < bi)) { best = d; bi = ix; }
        }
    }
    int r = 1;
    while (true) {
        const int lb = bkt - r - 1, rb = bkt + r + 1;
        const bool lv = (lb >= 0), rv = (rb <= NBKT - 1);
        const float lB = lv ? (et - (float)(bkt - r) / (float)NBKT) : FINF;
        const float rB = rv ? ((float)rb / (float)NBKT - et) : FINF;
        const bool needL = lv && !(best < lB);
        const bool needR = rv && !(best < rB);
        if (!needL && !needR) break;
        if (needL)
            for (int j = sbs[lb]; j < sbs[lb + 1]; ++j) {
                const float d = fabsf(et - sk[j]);
                const int ix = si[j];
                if (d < best || (d == best && ix < bi)) { best = d; bi = ix; }
            }
        if (needR)
            for (int j = sbs[rb]; j < sbs[rb + 1]; ++j) {
                const float d = fabsf(et - sk[j]);
                const int ix = si[j];
                if (d < best || (d == best && ix < bi)) { best = d; bi = ix; }
            }
        ++r;
    }

    const int slot = atomicAdd(&g_bar_cnt[b * TP + bi], 1);
    if (slot < CAP) g_ev_list[b * TP + bi][slot] = e;
}

// ---------------------------------------------------------------------------
// K2: float4 gather with SPECULATIVE first-chunk loads. The count load, the
// first 8 ID loads, and their value loads are all issued without waiting on
// each other (IDs are always valid in [0,TE) -> loads safe; accumulation is
// masked by j < m once the count arrives). Chain: IDs->values, count hidden.
// Layout: (q in [0,4)) x (d4 in [0,16)), 4 bars/block, grid 2048.
// ---------------------------------------------------------------------------
__global__ __launch_bounds__(256) void k_gather(
    const float* __restrict__ event_vals,
    float* __restrict__ out, int has_cov)
{
    __shared__ float4 xch[4][16];

    const int t   = threadIdx.x;
    const int grp = t >> 6;                     // 0..3 (bar within block)
    const int tg  = t & 63;                     // thread within group
    const int q   = tg >> 4;                    // 0..3 (event lane)
    const int d4  = tg & 15;                    // 0..15 (float4 chunk of dims)
    const int row = blockIdx.x * 4 + grp;       // 0 .. B*TP-1
    const int b   = row >> 11;

    const int* lst = g_ev_list[row];
    const float4* base =
        reinterpret_cast<const float4*>(event_vals + (size_t)b * TE * DD) + d4;

    // --- speculative issue: count + first 8 IDs, all independent ---
    const int n  = g_bar_cnt[row];
    const int ea = __ldg(&lst[q]);              // may be stale; in [0,TE)
    const int eb = __ldg(&lst[4 + q]);

    __syncthreads();                            // all count reads done...
    if (tg == 0) g_bar_cnt[row] = 0;            // ...before the reset

    // --- speculative value loads (depend only on IDs, not on count) ---
    const float4 va = __ldg(base + (size_t)ea * (DD / 4));
    const float4 vb = __ldg(base + (size_t)eb * (DD / 4));

    const int m = min(n, CAP);

    float4 acc = make_float4(0.f, 0.f, 0.f, 0.f);
    if (q < m) {                                // masked accumulate (exact)
        acc.x += va.x; acc.y += va.y; acc.z += va.z; acc.w += va.w;
    }
    if (4 + q < m) {
        acc.x += vb.x; acc.y += vb.y; acc.z += vb.z; acc.w += vb.w;
    }

    // --- rare tail: bars with more than 8 events ---
    for (int j0 = 8; j0 < m; j0 += 8) {
        const int ja = j0 + q;
        const int jb = j0 + 4 + q;
        const int fa = (ja < m) ? __ldg(&lst[ja]) : -1;
        const int fb = (jb < m) ? __ldg(&lst[jb]) : -1;
        if (fa >= 0) {
            const float4 v = __ldg(base + (size_t)fa * (DD / 4));
            acc.x += v.x; acc.y += v.y; acc.z += v.z; acc.w += v.w;
        }
        if (fb >= 0) {
            const float4 v = __ldg(base + (size_t)fb * (DD / 4));
            acc.x += v.x; acc.y += v.y; acc.z += v.z; acc.w += v.w;
        }
    }

    // reduce over q: xor-16 intra-warp, one smem exchange cross-warp
    acc.x += __shfl_xor_sync(0xffffffffu, acc.x, 16);
    acc.y += __shfl_xor_sync(0xffffffffu, acc.y, 16);
    acc.z += __shfl_xor_sync(0xffffffffu, acc.z, 16);
    acc.w += __shfl_xor_sync(0xffffffffu, acc.w, 16);

    if (q == 2) xch[grp][d4] = acc;
    __syncthreads();

    if (q == 0) {
        const float4 o = xch[grp][d4];
        const float inv = (n > 0) ? (1.0f / (float)n) : 0.0f;
        float4 r;
        r.x = (acc.x + o.x) * inv;
        r.y = (acc.y + o.y) * inv;
        r.z = (acc.z + o.z) * inv;
        r.w = (acc.w + o.w) * inv;
        reinterpret_cast<float4*>(out)[(size_t)row * (DD / 4) + d4] = r;
        if (has_cov && d4 == 0)
            out[(size_t)BB * TP * DD + row] = (n > 0) ? 1.0f : 0.0f;
    }
}

// ---------------------------------------------------------------------------
extern "C" void kernel_launch(void* const* d_in, const int* in_sizes, int n_in,
                              void* d_out, int out_size) {
    const float* price_ts   = (const float*)d_in[0];
    const float* event_ts   = (const float*)d_in[1];
    const float* event_vals = (const float*)d_in[2];
    float* out = (float*)d_out;

    const int has_cov = (out_size >= BB * TP * DD + BB * TP) ? 1 : 0;

    dim3 agrid(64, BB);
    k_align<<<agrid, 256>>>(price_ts, event_ts);

    k_gather<<<BB * TP / 4, 256>>>(event_vals, out, has_cov);
}

// round 16
// speedup vs baseline: 1.4511x; 1.0467x over previous
#include <cuda_runtime.h>
#include <cuda_bf16.h>

#define BB 4
#define TP 2048
#define TE 16384
#define DD 64
#define NBKT 1024
#define CAP 128
#define FINF 3.402823466e38f

// Scratch (allocation-free rule -> __device__ globals; zero-init at load).
// g_bar_cnt invariant: zero at kernel_launch entry (gather's owning warp
// resets it after reading).
// g_ev_list invariant: every slot always holds a value in [0, TE) (zero-init,
// only ever overwritten with valid event ids) -> speculative loads are safe.
__device__ int g_bar_cnt[BB * TP];
__device__ int g_ev_list[BB * TP][CAP];

__device__ __forceinline__ int warp_incl_scan(int v, int lane) {
    #pragma unroll
    for (int off = 1; off < 32; off <<= 1) {
        int u = __shfl_up_sync(0xffffffffu, v, off);
        if (lane >= off) v += u;
    }
    return v;
}

// ---------------------------------------------------------------------------
// K1: each block independently builds the price-bucket structure in its own
// smem (no cross-block sync), then runs the exact argmin for its 256 events
// and claims slots. Grid (64, BB) x 256.   [unchanged — R10-proven]
// ---------------------------------------------------------------------------
__global__ __launch_bounds__(256) void k_align(
    const float* __restrict__ price_ts,
    const float* __restrict__ event_ts)
{
    __shared__ float sk[TP];
    __shared__ int   si[TP];
    __shared__ int   sbs[NBKT + 1];
    __shared__ int   cnt[NBKT];
    __shared__ int   wsum[8];

    const int t = threadIdx.x;
    const int lane = t & 31, wid = t >> 5;
    const int x = blockIdx.x;          // 0..63
    const int b = blockIdx.y;          // 0..BB-1

    const int e = x * 256 + t;
    const float et = event_ts[b * TE + e];

    #pragma unroll
    for (int i = t; i < NBKT; i += 256) cnt[i] = 0;

    float pv[8]; int kb[8];
    #pragma unroll
    for (int j = 0; j < 8; ++j) {
        pv[j] = price_ts[b * TP + t + 256 * j];
        kb[j] = min((int)(pv[j] * (float)NBKT), NBKT - 1);
    }
    __syncthreads();
    #pragma unroll
    for (int j = 0; j < 8; ++j) atomicAdd(&cnt[kb[j]], 1);
    __syncthreads();

    const int c0 = cnt[4 * t], c1 = cnt[4 * t + 1];
    const int c2 = cnt[4 * t + 2], c3 = cnt[4 * t + 3];
    const int ts = c0 + c1 + c2 + c3;
    int incl = warp_incl_scan(ts, lane);
    if (lane == 31) wsum[wid] = incl;
    __syncthreads();
    if (t == 0) {
        int acc = 0;
        #pragma unroll
        for (int w = 0; w < 8; ++w) { int v = wsum[w]; wsum[w] = acc; acc += v; }
    }
    __syncthreads();
    const int base = wsum[wid] + (incl - ts);
    sbs[4 * t]     = base;
    sbs[4 * t + 1] = base + c0;
    sbs[4 * t + 2] = base + c0 + c1;
    sbs[4 * t + 3] = base + c0 + c1 + c2;
    if (t == 0) sbs[NBKT] = TP;
    #pragma unroll
    for (int i = t; i < NBKT; i += 256) cnt[i] = 0;
    __syncthreads();

    #pragma unroll
    for (int j = 0; j < 8; ++j) {
        const int pos = sbs[kb[j]] + atomicAdd(&cnt[kb[j]], 1);
        sk[pos] = pv[j];
        si[pos] = t + 256 * j;
    }
    __syncthreads();

    const int bkt = min(max((int)(et * (float)NBKT), 0), NBKT - 1);
    float best = FINF;
    int   bi   = 0x7fffffff;

    {
        const int j0 = sbs[max(bkt - 1, 0)];
        const int j1 = sbs[min(bkt + 1, NBKT - 1) + 1];
        for (int j = j0; j < j1; ++j) {
            const float d = fabsf(et - sk[j]);
            const int   ix = si[j];
            if (d < best || (d == best && ix < bi)) { best = d; bi = ix; }
        }
    }
    int r = 1;
    while (true) {
        const int lb = bkt - r - 1, rb = bkt + r + 1;
        const bool lv = (lb >= 0), rv = (rb <= NBKT - 1);
        const float lB = lv ? (et - (float)(bkt - r) / (float)NBKT) : FINF;
        const float rB = rv ? ((float)rb / (float)NBKT - et) : FINF;
        const bool needL = lv && !(best < lB);
        const bool needR = rv && !(best < rB);
        if (!needL && !needR) break;
        if (needL)
            for (int j = sbs[lb]; j < sbs[lb + 1]; ++j) {
                const float d = fabsf(et - sk[j]);
                const int ix = si[j];
                if (d < best || (d == best && ix < bi)) { best = d; bi = ix; }
            }
        if (needR)
            for (int j = sbs[rb]; j < sbs[rb + 1]; ++j) {
                const float d = fabsf(et - sk[j]);
                const int ix = si[j];
                if (d < best || (d == best && ix < bi)) { best = d; bi = ix; }
            }
        ++r;
    }

    const int slot = atomicAdd(&g_bar_cnt[b * TP + bi], 1);
    if (slot < CAP) g_ev_list[b * TP + bi][slot] = e;
}

// ---------------------------------------------------------------------------
// K2: warp-per-bar float4 gather, ZERO block barriers. Lane = (q in [0,2))
// x (d4 in [0,16)); each thread speculatively issues 4 independent LDG.128
// covering the first 8 events, masked-accumulates once the count arrives.
// Reduction over q = one shfl_xor(16). Warp-local counter reset. 8 bars per
// 256-thread block, grid 1024 = one fully-resident wave.
// ---------------------------------------------------------------------------
__global__ __launch_bounds__(256) void k_gather(
    const float* __restrict__ event_vals,
    float* __restrict__ out, int has_cov)
{
    const int t    = threadIdx.x;
    const int w    = t >> 5;                    // warp in block: 0..7
    const int lane = t & 31;
    const int q    = lane >> 4;                 // 0..1 (event lane)
    const int d4   = lane & 15;                 // 0..15 (float4 dim chunk)
    const int row  = blockIdx.x * 8 + w;        // 0 .. B*TP-1 (warp-private)
    const int b    = row >> 11;

    const int* lst = g_ev_list[row];
    const float4* base =
        reinterpret_cast<const float4*>(event_vals + (size_t)b * TE * DD) + d4;

    // speculative issue: count + 4 IDs, all independent
    const int n = g_bar_cnt[row];
    int ids[4];
    #pragma unroll
    for (int k = 0; k < 4; ++k)
        ids[k] = __ldg(&lst[q + 2 * k]);        // may be stale; in [0,TE)

    __syncwarp();                               // warp's reads precede...
    if (lane == 0) g_bar_cnt[row] = 0;          // ...the warp-local reset

    // speculative value loads: 4 independent LDG.128 per thread
    float4 v[4];
    #pragma unroll
    for (int k = 0; k < 4; ++k)
        v[k] = __ldg(base + (size_t)ids[k] * (DD / 4));

    const int m = min(n, CAP);

    float4 acc = make_float4(0.f, 0.f, 0.f, 0.f);
    #pragma unroll
    for (int k = 0; k < 4; ++k) {
        if (q + 2 * k < m) {                    // masked accumulate (exact)
            acc.x += v[k].x; acc.y += v[k].y;
            acc.z += v[k].z; acc.w += v[k].w;
        }
    }

    // rare tail: bars with more than 8 events
    for (int j0 = 8; j0 < m; j0 += 8) {
        int fid[4];
        #pragma unroll
        for (int k = 0; k < 4; ++k) {
            const int j = j0 + q + 2 * k;
            fid[k] = (j < m) ? __ldg(&lst[j]) : -1;
        }
        #pragma unroll
        for (int k = 0; k < 4; ++k) {
            if (fid[k] >= 0) {
                const float4 u = __ldg(base + (size_t)fid[k] * (DD / 4));
                acc.x += u.x; acc.y += u.y; acc.z += u.z; acc.w += u.w;
            }
        }
    }

    // reduce over q: single xor-16 shuffle set (no smem, no barrier)
    acc.x += __shfl_xor_sync(0xffffffffu, acc.x, 16);
    acc.y += __shfl_xor_sync(0xffffffffu, acc.y, 16);
    acc.z += __shfl_xor_sync(0xffffffffu, acc.z, 16);
    acc.w += __shfl_xor_sync(0xffffffffu, acc.w, 16);

    if (q == 0) {
        const float inv = (n > 0) ? (1.0f / (float)n) : 0.0f;
        float4 r;
        r.x = acc.x * inv; r.y = acc.y * inv;
        r.z = acc.z * inv; r.w = acc.w * inv;
        reinterpret_cast<float4*>(out)[(size_t)row * (DD / 4) + d4] = r;
        if (has_cov && d4 == 0)
            out[(size_t)BB * TP * DD + row] = (n > 0) ? 1.0f : 0.0f;
    }
}

// ---------------------------------------------------------------------------
extern "C" void kernel_launch(void* const* d_in, const int* in_sizes, int n_in,
                              void* d_out, int out_size) {
    const float* price_ts   = (const float*)d_in[0];
    const float* event_ts   = (const float*)d_in[1];
    const float* event_vals = (const float*)d_in[2];
    float* out = (float*)d_out;

    const int has_cov = (out_size >= BB * TP * DD + BB * TP) ? 1 : 0;

    dim3 agrid(64, BB);
    k_align<<<agrid, 256>>>(price_ts, event_ts);

    k_gather<<<BB * TP / 8, 256>>>(event_vals, out, has_cov);
}

// round 17
// speedup vs baseline: 1.4774x; 1.0181x over previous
#include <cuda_runtime.h>
#include <cuda_bf16.h>

#define BB 4
#define TP 2048
#define TE 16384
#define DD 64
#define NBKT 1024
#define CAP 128
#define FINF 3.402823466e38f

// Scratch (allocation-free rule -> __device__ globals; zero-init at load).
// g_bar_cnt invariant: zero at kernel_launch entry (gather's owning warp
// resets it after reading).
// g_ev_list invariant: every slot always holds a value in [0, TE) (zero-init,
// only ever overwritten with valid event ids) -> speculative loads are safe.
__device__ int g_bar_cnt[BB * TP];
__device__ int g_ev_list[BB * TP][CAP];

__device__ __forceinline__ int warp_incl_scan(int v, int lane) {
    #pragma unroll
    for (int off = 1; off < 32; off <<= 1) {
        int u = __shfl_up_sync(0xffffffffu, v, off);
        if (lane >= off) v += u;
    }
    return v;
}

// ---------------------------------------------------------------------------
// K1: 512 threads/block, 512 events/block, grid (32, BB) = 128 blocks.
// Each block builds the price-bucket structure in its own smem (half as many
// redundant builds as R16, wider build), then each thread runs the exact
// argmin for ONE event and claims a slot.
// ---------------------------------------------------------------------------
__global__ __launch_bounds__(512) void k_align(
    const float* __restrict__ price_ts,
    const float* __restrict__ event_ts)
{
    __shared__ float sk[TP];
    __shared__ int   si[TP];
    __shared__ int   sbs[NBKT + 1];
    __shared__ int   cnt[NBKT];
    __shared__ int   wsum[16];

    const int t = threadIdx.x;
    const int lane = t & 31, wid = t >> 5;
    const int x = blockIdx.x;          // 0..31
    const int b = blockIdx.y;          // 0..BB-1

    const int e = x * 512 + t;
    const float et = event_ts[b * TE + e];   // prefetch, overlaps the build

    // ---- build: 4 prices per thread ----
    #pragma unroll
    for (int i = t; i < NBKT; i += 512) cnt[i] = 0;

    float pv[4]; int kb[4];
    #pragma unroll
    for (int j = 0; j < 4; ++j) {
        pv[j] = price_ts[b * TP + t + 512 * j];
        kb[j] = min((int)(pv[j] * (float)NBKT), NBKT - 1);
    }
    __syncthreads();
    #pragma unroll
    for (int j = 0; j < 4; ++j) atomicAdd(&cnt[kb[j]], 1);
    __syncthreads();

    // exclusive scan of 1024 counts with 512 threads (2/thread)
    const int c0 = cnt[2 * t], c1 = cnt[2 * t + 1];
    const int ts = c0 + c1;
    int incl = warp_incl_scan(ts, lane);
    if (lane == 31) wsum[wid] = incl;
    __syncthreads();
    if (t == 0) {
        int acc = 0;
        #pragma unroll
        for (int w = 0; w < 16; ++w) { int v = wsum[w]; wsum[w] = acc; acc += v; }
    }
    __syncthreads();
    const int base = wsum[wid] + (incl - ts);
    sbs[2 * t]     = base;
    sbs[2 * t + 1] = base + c0;
    if (t == 0) sbs[NBKT] = TP;
    #pragma unroll
    for (int i = t; i < NBKT; i += 512) cnt[i] = 0;   // reuse as cursors
    __syncthreads();

    #pragma unroll
    for (int j = 0; j < 4; ++j) {
        const int pos = sbs[kb[j]] + atomicAdd(&cnt[kb[j]], 1);
        sk[pos] = pv[j];
        si[pos] = t + 512 * j;
    }
    __syncthreads();

    // ---- exact argmin (lexicographic (fabsf-dist, orig-idx) min; R4) ----
    const int bkt = min(max((int)(et * (float)NBKT), 0), NBKT - 1);
    float best = FINF;
    int   bi   = 0x7fffffff;

    {
        const int j0 = sbs[max(bkt - 1, 0)];
        const int j1 = sbs[min(bkt + 1, NBKT - 1) + 1];
        for (int j = j0; j < j1; ++j) {
            const float d = fabsf(et - sk[j]);
            const int   ix = si[j];
            if (d < best || (d == best && ix < bi)) { best = d; bi = ix; }
        }
    }
    int r = 1;
    while (true) {
        const int lb = bkt - r - 1, rb = bkt + r + 1;
        const bool lv = (lb >= 0), rv = (rb <= NBKT - 1);
        const float lB = lv ? (et - (float)(bkt - r) / (float)NBKT) : FINF;
        const float rB = rv ? ((float)rb / (float)NBKT - et) : FINF;
        const bool needL = lv && !(best < lB);
        const bool needR = rv && !(best < rB);
        if (!needL && !needR) break;
        if (needL)
            for (int j = sbs[lb]; j < sbs[lb + 1]; ++j) {
                const float d = fabsf(et - sk[j]);
                const int ix = si[j];
                if (d < best || (d == best && ix < bi)) { best = d; bi = ix; }
            }
        if (needR)
            for (int j = sbs[rb]; j < sbs[rb + 1]; ++j) {
                const float d = fabsf(et - sk[j]);
                const int ix = si[j];
                if (d < best || (d == best && ix < bi)) { best = d; bi = ix; }
            }
        ++r;
    }

    const int slot = atomicAdd(&g_bar_cnt[b * TP + bi], 1);
    if (slot < CAP) g_ev_list[b * TP + bi][slot] = e;
}

// ---------------------------------------------------------------------------
// K2: warp-per-bar float4 gather, ZERO block barriers. [unchanged — R16]
// ---------------------------------------------------------------------------
__global__ __launch_bounds__(256) void k_gather(
    const float* __restrict__ event_vals,
    float* __restrict__ out, int has_cov)
{
    const int t    = threadIdx.x;
    const int w    = t >> 5;                    // warp in block: 0..7
    const int lane = t & 31;
    const int q    = lane >> 4;                 // 0..1 (event lane)
    const int d4   = lane & 15;                 // 0..15 (float4 dim chunk)
    const int row  = blockIdx.x * 8 + w;        // 0 .. B*TP-1 (warp-private)
    const int b    = row >> 11;

    const int* lst = g_ev_list[row];
    const float4* base =
        reinterpret_cast<const float4*>(event_vals + (size_t)b * TE * DD) + d4;

    // speculative issue: count + 4 IDs, all independent
    const int n = g_bar_cnt[row];
    int ids[4];
    #pragma unroll
    for (int k = 0; k < 4; ++k)
        ids[k] = __ldg(&lst[q + 2 * k]);        // may be stale; in [0,TE)

    __syncwarp();                               // warp's reads precede...
    if (lane == 0) g_bar_cnt[row] = 0;          // ...the warp-local reset

    // speculative value loads: 4 independent LDG.128 per thread
    float4 v[4];
    #pragma unroll
    for (int k = 0; k < 4; ++k)
        v[k] = __ldg(base + (size_t)ids[k] * (DD / 4));

    const int m = min(n, CAP);

    float4 acc = make_float4(0.f, 0.f, 0.f, 0.f);
    #pragma unroll
    for (int k = 0; k < 4; ++k) {
        if (q + 2 * k < m) {                    // masked accumulate (exact)
            acc.x += v[k].x; acc.y += v[k].y;
            acc.z += v[k].z; acc.w += v[k].w;
        }
    }

    // rare tail: bars with more than 8 events
    for (int j0 = 8; j0 < m; j0 += 8) {
        int fid[4];
        #pragma unroll
        for (int k = 0; k < 4; ++k) {
            const int j = j0 + q + 2 * k;
            fid[k] = (j < m) ? __ldg(&lst[j]) : -1;
        }
        #pragma unroll
        for (int k = 0; k < 4; ++k) {
            if (fid[k] >= 0) {
                const float4 u = __ldg(base + (size_t)fid[k] * (DD / 4));
                acc.x += u.x; acc.y += u.y; acc.z += u.z; acc.w += u.w;
            }
        }
    }

    // reduce over q: single xor-16 shuffle set (no smem, no barrier)
    acc.x += __shfl_xor_sync(0xffffffffu, acc.x, 16);
    acc.y += __shfl_xor_sync(0xffffffffu, acc.y, 16);
    acc.z += __shfl_xor_sync(0xffffffffu, acc.z, 16);
    acc.w += __shfl_xor_sync(0xffffffffu, acc.w, 16);

    if (q == 0) {
        const float inv = (n > 0) ? (1.0f / (float)n) : 0.0f;
        float4 r;
        r.x = acc.x * inv; r.y = acc.y * inv;
        r.z = acc.z * inv; r.w = acc.w * inv;
        reinterpret_cast<float4*>(out)[(size_t)row * (DD / 4) + d4] = r;
        if (has_cov && d4 == 0)
            out[(size_t)BB * TP * DD + row] = (n > 0) ? 1.0f : 0.0f;
    }
}

// ---------------------------------------------------------------------------
extern "C" void kernel_launch(void* const* d_in, const int* in_sizes, int n_in,
                              void* d_out, int out_size) {
    const float* price_ts   = (const float*)d_in[0];
    const float* event_ts   = (const float*)d_in[1];
    const float* event_vals = (const float*)d_in[2];
    float* out = (float*)d_out;

    const int has_cov = (out_size >= BB * TP * DD + BB * TP) ? 1 : 0;

    dim3 agrid(32, BB);
    k_align<<<agrid, 512>>>(price_ts, event_ts);

    k_gather<<<BB * TP / 8, 256>>>(event_vals, out, has_cov);
}